// round 8
// baseline (speedup 1.0000x reference)
#include <cuda_runtime.h>
#include <math.h>
#include <stdint.h>

// LSTM: B=64, T=512, D=512, H=1024. Output: final h [64,1024] fp32.
//   gates = [x_t | h_{t-1}] @ [W ; U] + b  (fused K = 1536)
//   i,f,o = sigmoid, cbar = tanh; c = f*c + i*cbar; h = o*tanh(c)
//
// PERSISTENT kernel: 128 CTAs (1/SM, wave-1 co-resident), weights in SMEM
// (192KB/CTA, k-pair packed, gate-major: conflict-free LDS), cell state in
// registers for all 512 steps, SPLIT arrive/wait global barrier (wait hidden
// behind the x-only k-chunks of the next step). Mainloop: fma.rn.f32x2.

#define BB 64
#define TT 512
#define DD 512
#define HH 1024
#define GG 4096
#define KTOT 1536
#define NKP  (KTOT/2)        // 768 k-pairs
#define CHK 32               // k per A chunk
#define NCHK (KTOT/CHK)      // 48 chunks
#define XCHK (DD/CHK)        // 16 x-only chunks (k < D)
#define KPC (CHK/2)          // 16 k-pairs per chunk
#define NTHREADS 256
#define NCTA 128             // = HH/8; one CTA per 8 hidden cols
#define ASTRIDE 34           // A row stride (floats); conflict-free phases
#define ASZ (BB*ASTRIDE)

// smem: B2 (float2[NKP][32], gate-major) then 3 A buffers
#define B2_FLOATS (NKP*32*2)                  // 192KB
#define SMEM_FLOATS (B2_FLOATS + 3*ASZ)
#define SMEM_BYTES (SMEM_FLOATS*4)            // 222720 B < 227KB cap

__device__ float g_h[2][BB * HH];             // hidden ping-pong
__device__ unsigned long long g_bar = 0ULL;   // monotonic barrier counter

// Packed fp32x2 FMA (PTX-only form; one fma-pipe slot for two fp32 FMAs).
#define FFMA2(acc, a, b) \
    asm volatile("fma.rn.f32x2 %0, %1, %2, %0;" : "+l"(acc) : "l"(a), "l"(b))

__device__ __forceinline__ void cp_async8(uint32_t dst, const void* src) {
    asm volatile("cp.async.ca.shared.global [%0], [%1], 8;" :: "r"(dst), "l"(src));
}
__device__ __forceinline__ void cp_commit() {
    asm volatile("cp.async.commit_group;" ::: "memory");
}
template <int N>
__device__ __forceinline__ void cp_wait() {
    asm volatile("cp.async.wait_group %0;" :: "n"(N) : "memory");
}

__device__ __forceinline__ float sigmoidf_(float v) {
    return 1.0f / (1.0f + expf(-v));
}

__global__ __launch_bounds__(NTHREADS, 1)
void lstm_persistent(const float* __restrict__ x,
                     const float* __restrict__ W,
                     const float* __restrict__ U,
                     const float* __restrict__ bias,
                     float* __restrict__ out)
{
    extern __shared__ float smem[];
    float2* B2   = (float2*)smem;      // [kp*32 + g*8 + hloc] = {w(2kp,c), w(2kp+1,c)}
    float*  Abuf = smem + B2_FLOATS;   // 3 buffers of [row][k], stride ASTRIDE

    const int tid  = threadIdx.x;
    const int jb   = blockIdx.x;
    const int j0   = jb * 8;
    const int w    = tid >> 5;
    const int lane = tid & 31;

    // Output mapping: hidden col j = j0 + (lane&7); rows rowb=w*4+(lane>>3), rowb+32.
    const int jloc = lane & 7;
    const int rowb = w * 4 + (lane >> 3);
    const int j    = j0 + jloc;

    // ---- one-time: stage weight slice into SMEM, k-pair packed, GATE-MAJOR ----
    // (gate-major => per-warp B reads are 8 distinct addresses x 4-lane
    //  broadcast over 16 distinct banks: conflict-free LDS.64)
    {
        const int kq = tid >> 3;                  // 0..31
        const int hq = tid & 7;                   // 0..7
        for (int i = 0; i < NCHK; ++i) {
            const int k = i * CHK + kq;
            const float* wr = (k < DD) ? (W + (size_t)k * GG)
                                       : (U + (size_t)(k - DD) * GG);
            const int kp  = k >> 1;
            const int par = k & 1;
            #pragma unroll
            for (int g = 0; g < 4; ++g) {
                float v = wr[g * HH + j0 + hq];
                ((float*)&B2[kp * 32 + g * 8 + hq])[par] = v;
            }
        }
    }

    // zero h buffer 0 (t=0 input)
    {
        float* h0 = &g_h[0][0] + (size_t)jb * 512;
        h0[tid]       = 0.0f;
        h0[tid + 256] = 0.0f;
    }

    const float bi = bias[j];
    const float bf = bias[HH + j];
    const float bc = bias[2 * HH + j];
    const float bo = bias[3 * HH + j];

    float c0 = 0.0f, c1 = 0.0f;                   // register-resident cell state

    // cp.async decode: 4 slots/thread; rows (tid>>4)+{0,16,32,48}, 8B each
    const int a_r    = tid >> 4;
    const int a_koff = (tid & 15) * 2;

    // ---- split global barrier (monotonic counter; graph-replay safe) ----
    unsigned long long bar_tgt = 0;   // meaningful in tid0 only

    #define GBAR_ARRIVE()                                                       \
    {                                                                           \
        __syncthreads();  /* all block stores precede tid0's release */         \
        if (tid == 0) {                                                         \
            __threadfence();                                                    \
            unsigned long long old_ = atomicAdd(&g_bar, 1ULL);                  \
            bar_tgt = (old_ / NCTA) * NCTA + NCTA;                              \
        }                                                                       \
    }
    #define GBAR_WAIT()                                                         \
    {                                                                           \
        if (tid == 0) {                                                         \
            while (*((volatile unsigned long long*)&g_bar) < bar_tgt)           \
                __nanosleep(64);                                                \
            __threadfence();                                                    \
        }                                                                       \
        __syncthreads();                                                        \
    }

    GBAR_ARRIVE();            // publish weights + h-zero
    GBAR_WAIT();

    for (int t = 0; t < TT; ++t) {
        const float* xt  = x + (size_t)t * DD;          // + row*TT*DD
        const float* hin = &g_h[t & 1][0];

        unsigned long long acc0[4] = {0ull,0ull,0ull,0ull};
        unsigned long long acc1[4] = {0ull,0ull,0ull,0ull};

        #define PREFETCH(cidx)                                                  \
        {                                                                       \
            const int k0_ = (cidx) * CHK;                                       \
            float* dst0 = Abuf + ((cidx) % 3) * ASZ;                            \
            const float* sb; int sstride;                                       \
            if (k0_ < DD) { sb = xt + k0_;          sstride = TT * DD; }        \
            else          { sb = hin + (k0_ - DD);  sstride = HH; }             \
            _Pragma("unroll")                                                   \
            for (int i_ = 0; i_ < 4; ++i_) {                                    \
                int r_ = a_r + i_ * 16;                                         \
                uint32_t d_ = (uint32_t)__cvta_generic_to_shared(               \
                    dst0 + r_ * ASTRIDE + a_koff);                              \
                cp_async8(d_, sb + (size_t)r_ * sstride + a_koff);              \
            }                                                                   \
            cp_commit();                                                        \
        }

        #define COMPUTE(cidx)                                                   \
        {                                                                       \
            const float* A = Abuf + ((cidx) % 3) * ASZ;                         \
            const float2* Bp = B2 + (size_t)((cidx) * KPC) * 32 + jloc;         \
            _Pragma("unroll")                                                   \
            for (int kpl = 0; kpl < KPC; ++kpl) {                               \
                const unsigned long long a0 =                                   \
                    *(const unsigned long long*)(A + rowb * ASTRIDE + 2 * kpl); \
                const unsigned long long a1 =                                   \
                    *(const unsigned long long*)(A + (rowb + 32) * ASTRIDE + 2 * kpl); \
                const unsigned long long b0 =                                   \
                    *(const unsigned long long*)(Bp + (size_t)kpl * 32);        \
                const unsigned long long b1 =                                   \
                    *(const unsigned long long*)(Bp + (size_t)kpl * 32 + 8);    \
                const unsigned long long b2 =                                   \
                    *(const unsigned long long*)(Bp + (size_t)kpl * 32 + 16);   \
                const unsigned long long b3 =                                   \
                    *(const unsigned long long*)(Bp + (size_t)kpl * 32 + 24);   \
                FFMA2(acc0[0], a0, b0);  FFMA2(acc1[0], a1, b0);                \
                FFMA2(acc0[1], a0, b1);  FFMA2(acc1[1], a1, b1);                \
                FFMA2(acc0[2], a0, b2);  FFMA2(acc1[2], a1, b2);                \
                FFMA2(acc0[3], a0, b3);  FFMA2(acc1[3], a1, b3);                \
            }                                                                   \
        }

        // ---- x-phase: chunks 0..15 depend only on x, not on h ----
        PREFETCH(0);
        for (int c = 0; c < XCHK; ++c) {
            if (c + 1 < XCHK) { PREFETCH(c + 1); cp_wait<1>(); }
            else              { cp_wait<0>(); }
            __syncthreads();
            COMPUTE(c);
        }

        // ---- barrier wait hidden behind the x-phase above ----
        if (t > 0) GBAR_WAIT();   // h of step t-1 now globally visible

        // ---- h-phase: chunks 16..47 ----
        PREFETCH(XCHK);
        for (int c = XCHK; c < NCHK; ++c) {
            if (c + 1 < NCHK) { PREFETCH(c + 1); cp_wait<1>(); }
            else              { cp_wait<0>(); }
            __syncthreads();
            COMPUTE(c);
        }

        // ---- epilogue: unpack {even-k, odd-k} partials, LSTM pointwise ----
        float g0[4], g1[4];
        #pragma unroll
        for (int q = 0; q < 4; ++q) {
            float lo, hi;
            asm("mov.b64 {%0, %1}, %2;" : "=f"(lo), "=f"(hi) : "l"(acc0[q]));
            g0[q] = lo + hi;
            asm("mov.b64 {%0, %1}, %2;" : "=f"(lo), "=f"(hi) : "l"(acc1[q]));
            g1[q] = lo + hi;
        }

        float* hout = (t == TT - 1) ? out : &g_h[(t + 1) & 1][0];

        {
            const float iv = sigmoidf_(g0[0] + bi);
            const float fv = sigmoidf_(g0[1] + bf);
            const float cv = tanhf   (g0[2] + bc);
            const float ov = sigmoidf_(g0[3] + bo);
            c0 = fv * c0 + iv * cv;
            hout[(size_t)rowb * HH + j] = ov * tanhf(c0);
        }
        {
            const float iv = sigmoidf_(g1[0] + bi);
            const float fv = sigmoidf_(g1[1] + bf);
            const float cv = tanhf   (g1[2] + bc);
            const float ov = sigmoidf_(g1[3] + bo);
            c1 = fv * c1 + iv * cv;
            hout[(size_t)(rowb + 32) * HH + j] = ov * tanhf(c1);
        }

        if (t < TT - 1) GBAR_ARRIVE();   // release h of step t
    }
}

extern "C" void kernel_launch(void* const* d_in, const int* in_sizes, int n_in,
                              void* d_out, int out_size)
{
    const float* x    = (const float*)d_in[0];  // [64, 512, 512]
    const float* W    = (const float*)d_in[1];  // [512, 4096]
    const float* U    = (const float*)d_in[2];  // [1024, 4096]
    const float* bias = (const float*)d_in[3];  // [4096]
    float* out = (float*)d_out;                 // [64, 1024]

    cudaFuncSetAttribute(lstm_persistent,
                         cudaFuncAttributeMaxDynamicSharedMemorySize, SMEM_BYTES);

    lstm_persistent<<<NCTA, NTHREADS, SMEM_BYTES>>>(x, W, U, bias, out);
}